// round 14
// baseline (speedup 1.0000x reference)
#include <cuda_runtime.h>
#include <cuda_bf16.h>
#include <math.h>
#include <stdint.h>

#define B_   512
#define L_   512
#define KK_  10

// ---------------- scratch (device globals; no allocations) ----------------
__device__ __align__(16) uint32_t g_h1[B_ * L_ * 56];   // h1 bf16x2 [b][l][112ch]
__device__ float    g_logits[B_ * L_];
__device__ float    g_hpart[B_ * 4 * 128];
__device__ float    g_gz[B_ * 128];
__device__ __align__(16) __nv_bfloat16 g_Wb1[3 * 128 * 120];  // [tap][f][k pad120]
__device__ __align__(16) __nv_bfloat16 g_Wb2[3 * 128 * 120];
__device__ __align__(16) __nv_bfloat16 g_WbL[3 * 128 * 120];
__device__ __align__(16) __nv_bfloat16 g_Wb3[112 * 120];      // conv3 loc half

// ---------------- K0: weight prep -> padded bf16 blobs ---------------------
__global__ void k0_prep(const float* __restrict__ w1, const float* __restrict__ w2,
                        const float* __restrict__ wl, const float* __restrict__ w3) {
    int id = blockIdx.x * 256 + threadIdx.x;
    if (id >= 151680) return;
    if (id < 138240) {
        int conv = id / 46080, rem = id - conv * 46080;
        int t = rem / 15360, p = rem - t * 15360;
        int f = p / 120, k = p - f * 120;
        float v = 0.f;
        const float* src = (conv == 0) ? w1 : (conv == 1) ? w2 : wl;
        if (f < 100 && k < 100) v = src[f * 300 + k * 3 + t];
        __nv_bfloat16* dst = (conv == 0) ? g_Wb1 : (conv == 1) ? g_Wb2 : g_WbL;
        dst[t * 15360 + f * 120 + k] = __float2bfloat16(v);
    } else {
        int p = id - 138240;
        int f = p / 120, k = p - f * 120;
        float v = 0.f;
        if (f < 100 && k < 100) v = w3[f * 200 + 100 + k];
        g_Wb3[p] = __float2bfloat16(v);
    }
}

// ---------------- PTX primitives -------------------------------------------
__device__ __forceinline__ uint32_t smem_u32(const void* p) {
    uint32_t a;
    asm("{ .reg .u64 t; cvta.to.shared.u64 t, %1; cvt.u32.u64 %0, t; }" : "=r"(a) : "l"(p));
    return a;
}
__device__ __forceinline__ void ldsm_x4(uint32_t& a0, uint32_t& a1, uint32_t& a2,
                                        uint32_t& a3, uint32_t addr) {
    asm volatile("ldmatrix.sync.aligned.m8n8.x4.shared.b16 {%0,%1,%2,%3}, [%4];"
                 : "=r"(a0), "=r"(a1), "=r"(a2), "=r"(a3) : "r"(addr));
}
__device__ __forceinline__ void ldsm_x2(uint32_t& b0, uint32_t& b1, uint32_t addr) {
    asm volatile("ldmatrix.sync.aligned.m8n8.x2.shared.b16 {%0,%1}, [%2];"
                 : "=r"(b0), "=r"(b1) : "r"(addr));
}
__device__ __forceinline__ void mma16816(float* d, uint32_t a0, uint32_t a1,
                                         uint32_t a2, uint32_t a3,
                                         uint32_t b0, uint32_t b1) {
    asm volatile("mma.sync.aligned.m16n8k16.row.col.f32.bf16.bf16.f32 "
                 "{%0,%1,%2,%3},{%4,%5,%6,%7},{%8,%9},{%0,%1,%2,%3};"
                 : "+f"(d[0]), "+f"(d[1]), "+f"(d[2]), "+f"(d[3])
                 : "r"(a0), "r"(a1), "r"(a2), "r"(a3), "r"(b0), "r"(b1));
}
__device__ __forceinline__ float2 bf2f(uint32_t u) {
    __nv_bfloat162 h = *(__nv_bfloat162*)&u;
    return make_float2(__bfloat162float(h.x), __bfloat162float(h.y));
}
__device__ __forceinline__ void cpa16(uint32_t d, const void* s) {
    asm volatile("cp.async.cg.shared.global [%0], [%1], 16;" :: "r"(d), "l"(s));
}
__device__ __forceinline__ void cpa16z(uint32_t d, const void* s, int sz) {
    asm volatile("cp.async.cg.shared.global [%0], [%1], 16, %2;" :: "r"(d), "l"(s), "r"(sz));
}
__device__ __forceinline__ void cpa_commit() {
    asm volatile("cp.async.commit_group;" ::: "memory");
}
__device__ __forceinline__ void cpa_wait0() {
    asm volatile("cp.async.wait_group 0;" ::: "memory");
}

// ---------------- single-tap conv GEMM (proven core) -----------------------
__device__ __forceinline__ void gemm_tap(uint32_t sData_u, uint32_t wb_u,
                                         float (&d)[2][7][4], int rshift,
                                         int lane, int wf, int wl) {
    const int lam = lane & 15;
#pragma unroll
    for (int ks = 0; ks < 7; ks++) {
        uint32_t b0[7], b1[7];
#pragma unroll
        for (int nf = 0; nf < 7; nf++) {
            uint32_t addr = wb_u + (uint32_t)(wf * 56 + nf * 8 + (lam & 7)) * 240
                          + ks * 32 + ((lam >> 3) & 1) * 16;
            ldsm_x2(b0[nf], b1[nf], addr);
        }
#pragma unroll
        for (int mi = 0; mi < 2; mi++) {
            uint32_t addr = sData_u + (uint32_t)(wl * 32 + mi * 16 + rshift + lam) * 240
                          + ks * 32 + (lane >> 4) * 16;
            uint32_t a0, a1, a2, a3;
            ldsm_x4(a0, a1, a2, a3, addr);
#pragma unroll
            for (int nf = 0; nf < 7; nf++)
                mma16816(d[mi][nf], a0, a1, a2, a3, b0[nf], b1[nf]);
        }
    }
}
#define ZERO_D(dd) do {                                                        \
    _Pragma("unroll") for (int mi = 0; mi < 2; mi++)                           \
    _Pragma("unroll") for (int nf = 0; nf < 7; nf++)                           \
    _Pragma("unroll") for (int q = 0; q < 4; q++) (dd)[mi][nf][q] = 0.f;       \
} while (0)

// staging source for kCF pipeline step s (0..6): conv2 taps, li taps, w3
__device__ __forceinline__ const uint4* wsrc(int s) {
    if (s < 3) return ((const uint4*)g_Wb2) + s * 1920;
    if (s < 6) return ((const uint4*)g_WbL) + (s - 3) * 1920;
    return (const uint4*)g_Wb3;
}
__device__ __forceinline__ void stage_w(uint32_t dst_u, const uint4* src, int tid) {
    for (int i = tid; i < 1680; i += 256) cpa16(dst_u + i * 16, src + i);
    cpa_commit();
}

// ---------------- KC1: emb gather + conv1 -> h1 + hmean partials -----------
#define C1_W    31200
#define C1_BIAS 111840
#define C1_HS   112352
#define C1_SMEM 112800
__global__ __launch_bounds__(256, 2) void kC1(const int* __restrict__ x,
                                              const float* __restrict__ emb,
                                              const float* __restrict__ b1) {
    extern __shared__ char sm[];
    uint32_t* sD32 = (uint32_t*)sm;
    float* sBias = (float*)(sm + C1_BIAS);
    float* sHs = (float*)(sm + C1_HS);
    const int cx = blockIdx.x, b = blockIdx.y, tid = threadIdx.x;
    const int lane = tid & 31, wid = tid >> 5, wf = wid & 1, wl = wid >> 1;
    const int l0 = cx * 128;
    const int* xb = x + b * L_;
    const float4* e4 = (const float4*)emb;
    const uint32_t sData_u = smem_u32(sm), sW_u = sData_u + C1_W;

    {
        const uint4* ws = (const uint4*)g_Wb1;
        for (int i = tid; i < 5040; i += 256) {
            int t = i / 1680, r = i - t * 1680;
            cpa16(sW_u + (t * 1680 + r) * 16, ws + t * 1920 + r);
        }
        cpa_commit();
    }
    // float4 gather: 130 rows x 30 items (25 data + 5 zero-pad)
    for (int idx = tid; idx < 130 * 30; idx += 256) {
        int r = idx / 30, c = idx - r * 30;
        int l = l0 - 1 + r;
        uint32_t pk0 = 0, pk1 = 0;
        if ((unsigned)l < (unsigned)L_ && c < 25) {
            int tok = xb[l];
            float4 v = e4[tok * 25 + c];
            __nv_bfloat162 h0 = __floats2bfloat162_rn(v.x, v.y);
            __nv_bfloat162 h1 = __floats2bfloat162_rn(v.z, v.w);
            pk0 = *(uint32_t*)&h0; pk1 = *(uint32_t*)&h1;
        }
        sD32[r * 60 + c * 2] = pk0;
        sD32[r * 60 + c * 2 + 1] = pk1;
    }
    if (tid < 128) sBias[tid] = (tid < 100) ? b1[tid] : 0.f;
    if (tid < 112) sHs[tid] = 0.f;
    cpa_wait0();
    __syncthreads();

    float d[2][7][4];
    ZERO_D(d);
    gemm_tap(sData_u, sW_u, d, 0, lane, wf, wl);
    gemm_tap(sData_u, sW_u + 26880, d, 1, lane, wf, wl);
    gemm_tap(sData_u, sW_u + 53760, d, 2, lane, wf, wl);
    __syncthreads();                     // all data-region reads complete

    const int lq = lane >> 2, fq = lane & 3;
    float acc[7][2];
#pragma unroll
    for (int nf = 0; nf < 7; nf++) { acc[nf][0] = 0.f; acc[nf][1] = 0.f; }
#pragma unroll
    for (int mi = 0; mi < 2; mi++) {
        int lr = wl * 32 + mi * 16 + lq;
#pragma unroll
        for (int nf = 0; nf < 7; nf++) {
            int fp = wf * 28 + nf * 4 + fq;
            float bx = sBias[2 * fp], by = sBias[2 * fp + 1];
            float v0 = fmaxf(d[mi][nf][0] + bx, 0.f), v1 = fmaxf(d[mi][nf][1] + by, 0.f);
            float v2 = fmaxf(d[mi][nf][2] + bx, 0.f), v3 = fmaxf(d[mi][nf][3] + by, 0.f);
            __nv_bfloat162 p0 = __floats2bfloat162_rn(v0, v1);
            __nv_bfloat162 p1 = __floats2bfloat162_rn(v2, v3);
            sD32[lr * 60 + fp] = *(uint32_t*)&p0;
            sD32[(lr + 8) * 60 + fp] = *(uint32_t*)&p1;
            acc[nf][0] += v0 + v2;
            acc[nf][1] += v1 + v3;
        }
    }
#pragma unroll
    for (int nf = 0; nf < 7; nf++)
#pragma unroll
        for (int j = 0; j < 2; j++) {
            float v = acc[nf][j];
            v += __shfl_xor_sync(0xffffffffu, v, 4);
            v += __shfl_xor_sync(0xffffffffu, v, 8);
            v += __shfl_xor_sync(0xffffffffu, v, 16);
            if (lane < 4) atomicAdd(&sHs[wf * 56 + nf * 8 + fq * 2 + j], v);
        }
    __syncthreads();
    {
        uint4* dst4 = (uint4*)(g_h1 + ((size_t)b * L_ + l0) * 56);
        const uint4* src4 = (const uint4*)sD32;
        for (int idx = tid; idx < 128 * 14; idx += 256) {
            int row = idx / 14, q = idx - row * 14;
            dst4[row * 14 + q] = src4[row * 15 + q];
        }
    }
    if (tid < 112) g_hpart[(b * 4 + cx) * 128 + tid] = sHs[tid];
}

// ---------------- KG: hmean -> g -> gz -------------------------------------
__global__ __launch_bounds__(128) void kG(const float* __restrict__ giw,
                                          const float* __restrict__ gib,
                                          const float* __restrict__ c3w,
                                          const float* __restrict__ c3b) {
    const int b = blockIdx.x, tid = threadIdx.x;
    __shared__ float shm[100], sg[100];
    if (tid < 100) {
        const float* p = g_hpart + b * 4 * 128 + tid;
        shm[tid] = (p[0] + p[128] + p[256] + p[384]) * (1.f / (float)L_);
    }
    __syncthreads();
    if (tid < 100) {
        float a = gib[tid];
        const float* wr = &giw[tid * 100];
        for (int f = 0; f < 100; f++) a = fmaf(wr[f], shm[f], a);
        sg[tid] = fmaxf(a, 0.f);
    }
    __syncthreads();
    if (tid < 100) {
        float a = c3b[tid];
        const float* wr = &c3w[tid * 200];
        for (int h = 0; h < 100; h++) a = fmaf(wr[h], sg[h], a);
        g_gz[b * 128 + tid] = a;
    }
}

// ---------------- KCF: fused conv2 -> li -> conv3 -> logits ----------------
// smem: DH [132][120]bf16 @0 (31680) | wslots W0/W1/W2 @31680/58560/85440
// (3 x 26880) | b2 @112320 | lb @112832 | gz @113344 | c4 @113856
// | sLog @114368 (512) => 114880 B (2 CTAs/SM: 229.8 KB <= 233 KB)
#define CF_W0   31680
#define CF_W1   58560
#define CF_W2   85440
#define CF_B2   112320
#define CF_BL   112832
#define CF_GZ   113344
#define CF_C4   113856
#define CF_LOG  114368
#define CF_SMEM 114880
__global__ __launch_bounds__(256, 2) void kCF(const float* __restrict__ b2,
                                              const float* __restrict__ lb,
                                              const float* __restrict__ c4w,
                                              const float* __restrict__ c4b) {
    extern __shared__ char sm[];
    uint32_t* sD32 = (uint32_t*)sm;                 // D1, then H2, then Loc
    __nv_bfloat16* sD16 = (__nv_bfloat16*)sm;
    float* sB2 = (float*)(sm + CF_B2);
    float* sBL = (float*)(sm + CF_BL);
    float* sGz = (float*)(sm + CF_GZ);
    float* sC4 = (float*)(sm + CF_C4);
    float* sLog = (float*)(sm + CF_LOG);
    const int cx = blockIdx.x, b = blockIdx.y, tid = threadIdx.x;
    const int lane = tid & 31, wid = tid >> 5, wf = wid & 1, wl = wid >> 1;
    const int l0 = cx * 128;
    const uint4* src = (const uint4*)(g_h1 + (size_t)b * L_ * 56);
    const uint32_t sD_u = smem_u32(sm);
    const uint32_t w0 = sD_u + CF_W0, w1 = sD_u + CF_W1, w2 = sD_u + CF_W2;

    // stage conv2 taps 0..2 and D1 tile; single wait covers all
    stage_w(w0, wsrc(0), tid);
    stage_w(w1, wsrc(1), tid);
    stage_w(w2, wsrc(2), tid);
    for (int idx = tid; idx < 132 * 15; idx += 256) {
        int r = idx / 15, q = idx - r * 15;
        int l = l0 - 2 + r;
        bool ok = (q < 14) && ((unsigned)l < (unsigned)L_);
        const void* s = ok ? (const void*)(src + (size_t)l * 14 + q) : (const void*)src;
        cpa16z(sD_u + (uint32_t)idx * 16, s, ok ? 16 : 0);
    }
    cpa_commit();
    if (tid < 128) {
        sB2[tid] = (tid < 100) ? b2[tid] : 0.f;
        sBL[tid] = (tid < 100) ? lb[tid] : 0.f;
        sGz[tid] = (tid < 100) ? g_gz[b * 128 + tid] : 0.f;
        sC4[tid] = (tid < 100) ? c4w[tid] : 0.f;
        sLog[tid] = 0.f;
    }
    cpa_wait0();
    __syncthreads();

    const int lq = lane >> 2, fq = lane & 3;
    const int hcol = tid / 112, hch = tid - hcol * 112;
    const bool hok = (tid < 224) &&
        ((hcol == 0) ? (l0 - 1 >= 0) : (l0 + 128 < L_));
    float hs = 0.f;

    float d[2][7][4];
    ZERO_D(d);
    // ---- conv2: 3 gemms back-to-back, no internal syncs ----
    gemm_tap(sD_u, w0, d, 1, lane, wf, wl);
    gemm_tap(sD_u, w1, d, 2, lane, wf, wl);
    gemm_tap(sD_u, w2, d, 3, lane, wf, wl);
    if (hok) {
#pragma unroll
        for (int t = 0; t < 3; t++) {
            const uint32_t* dr = sD32 + ((hcol ? 129 : 0) + t) * 60;
            const uint4* wr4 = (const uint4*)(g_Wb2 + t * 15360 + hch * 120);
#pragma unroll
            for (int q = 0; q < 13; q++) {
                uint4 w = wr4[q];
                float2 w0_ = bf2f(w.x), w1_ = bf2f(w.y), w2_ = bf2f(w.z), w3_ = bf2f(w.w);
                float2 a0 = bf2f(dr[4 * q]), a1 = bf2f(dr[4 * q + 1]);
                float2 a2 = bf2f(dr[4 * q + 2]), a3 = bf2f(dr[4 * q + 3]);
                hs += a0.x * w0_.x + a0.y * w0_.y + a1.x * w1_.x + a1.y * w1_.y
                    + a2.x * w2_.x + a2.y * w2_.y + a3.x * w3_.x + a3.y * w3_.y;
            }
        }
    }
    __syncthreads();                      // D1 reads done

    // stage li taps during H2 epilogue
    stage_w(w0, wsrc(3), tid);
    stage_w(w1, wsrc(4), tid);
    stage_w(w2, wsrc(5), tid);
    // H2 overwrites D1 region (rows 0..129)
#pragma unroll
    for (int mi = 0; mi < 2; mi++) {
        int lr = wl * 32 + mi * 16 + lq;
#pragma unroll
        for (int nf = 0; nf < 7; nf++) {
            int fp = wf * 28 + nf * 4 + fq;
            float bx = sB2[2 * fp], by = sB2[2 * fp + 1];
            float v0 = fmaxf(d[mi][nf][0] + bx, 0.f), v1 = fmaxf(d[mi][nf][1] + by, 0.f);
            float v2 = fmaxf(d[mi][nf][2] + bx, 0.f), v3 = fmaxf(d[mi][nf][3] + by, 0.f);
            __nv_bfloat162 p0 = __floats2bfloat162_rn(v0, v1);
            __nv_bfloat162 p1 = __floats2bfloat162_rn(v2, v3);
            sD32[(lr + 1) * 60 + fp] = *(uint32_t*)&p0;
            sD32[(lr + 9) * 60 + fp] = *(uint32_t*)&p1;
        }
    }
    if (tid < 224) {
        float v = hok ? fmaxf(hs + sB2[hch], 0.f) : 0.f;
        sD16[(hcol ? 129 : 0) * 120 + hch] = __float2bfloat16(v);
    }
    cpa_wait0();
    __syncthreads();

    // ---- li: 3 gemms back-to-back over H2 ----
    ZERO_D(d);
    gemm_tap(sD_u, w0, d, 0, lane, wf, wl);
    gemm_tap(sD_u, w1, d, 1, lane, wf, wl);
    gemm_tap(sD_u, w2, d, 2, lane, wf, wl);
    __syncthreads();                      // H2 reads done

    // stage w3 during Loc epilogue
    stage_w(w0, wsrc(6), tid);
    // Loc = relu(D + lb) -> DH rows 0..127
#pragma unroll
    for (int mi = 0; mi < 2; mi++) {
        int lr = wl * 32 + mi * 16 + lq;
#pragma unroll
        for (int nf = 0; nf < 7; nf++) {
            int fp = wf * 28 + nf * 4 + fq;
            float bx = sBL[2 * fp], by = sBL[2 * fp + 1];
            float v0 = fmaxf(d[mi][nf][0] + bx, 0.f), v1 = fmaxf(d[mi][nf][1] + by, 0.f);
            float v2 = fmaxf(d[mi][nf][2] + bx, 0.f), v3 = fmaxf(d[mi][nf][3] + by, 0.f);
            __nv_bfloat162 p0 = __floats2bfloat162_rn(v0, v1);
            __nv_bfloat162 p1 = __floats2bfloat162_rn(v2, v3);
            sD32[lr * 60 + fp] = *(uint32_t*)&p0;
            sD32[(lr + 8) * 60 + fp] = *(uint32_t*)&p1;
        }
    }
    cpa_wait0();
    __syncthreads();

    // ---- conv3 loc half + fused conv4 -> logits ----
    ZERO_D(d);
    gemm_tap(sD_u, w0, d, 0, lane, wf, wl);
#pragma unroll
    for (int mi = 0; mi < 2; mi++) {
        int lr = wl * 32 + mi * 16 + lq;
        float pA = 0.f, pB = 0.f;
#pragma unroll
        for (int nf = 0; nf < 7; nf++) {
            int f0 = wf * 56 + nf * 8 + fq * 2;
            float g0 = sGz[f0], g1 = sGz[f0 + 1];
            float c0 = sC4[f0], c1 = sC4[f0 + 1];
            pA += c0 * fmaxf(d[mi][nf][0] + g0, 0.f) + c1 * fmaxf(d[mi][nf][1] + g1, 0.f);
            pB += c0 * fmaxf(d[mi][nf][2] + g0, 0.f) + c1 * fmaxf(d[mi][nf][3] + g1, 0.f);
        }
        pA += __shfl_xor_sync(0xffffffffu, pA, 1);
        pA += __shfl_xor_sync(0xffffffffu, pA, 2);
        pB += __shfl_xor_sync(0xffffffffu, pB, 1);
        pB += __shfl_xor_sync(0xffffffffu, pB, 2);
        if (fq == 0) {
            atomicAdd(&sLog[lr], pA);
            atomicAdd(&sLog[lr + 8], pB);
        }
    }
    __syncthreads();
    if (tid < 128) g_logits[b * L_ + l0 + tid] = sLog[tid] + c4b[0];
}

// ---------------- block reductions (256 threads) ---------------------------
__device__ __forceinline__ float bmax256(float v, float* sred) {
#pragma unroll
    for (int o = 16; o > 0; o >>= 1) v = fmaxf(v, __shfl_xor_sync(0xffffffffu, v, o));
    int w = threadIdx.x >> 5;
    if ((threadIdx.x & 31) == 0) sred[w] = v;
    __syncthreads();
    if (threadIdx.x == 0) {
        float t = sred[0];
#pragma unroll
        for (int i = 1; i < 8; i++) t = fmaxf(t, sred[i]);
        sred[0] = t;
    }
    __syncthreads();
    float r = sred[0];
    __syncthreads();
    return r;
}
__device__ __forceinline__ float bsum256(float v, float* sred) {
#pragma unroll
    for (int o = 16; o > 0; o >>= 1) v += __shfl_xor_sync(0xffffffffu, v, o);
    int w = threadIdx.x >> 5;
    if ((threadIdx.x & 31) == 0) sred[w] = v;
    __syncthreads();
    if (threadIdx.x == 0) {
        float t = sred[0];
#pragma unroll
        for (int i = 1; i < 8; i++) t += sred[i];
        sred[0] = t;
    }
    __syncthreads();
    float r = sred[0];
    __syncthreads();
    return r;
}

// ---------------- KS: gumbel softmax + pooling + MLP + sigmoid (fused) -----
__global__ __launch_bounds__(256) void kS(const float* __restrict__ u,
                                          const int* __restrict__ x,
                                          const float* __restrict__ emb,
                                          const float* __restrict__ f1w,
                                          const float* __restrict__ f1b,
                                          const float* __restrict__ hw,
                                          const float* __restrict__ hb,
                                          float* __restrict__ cs_out,
                                          float* __restrict__ out) {
    const int b = blockIdx.x, tid = threadIdx.x;
    __shared__ float slog[L_];
    __shared__ float scs[L_];
    __shared__ int sx[L_];
    __shared__ float spool2[2][128];
    __shared__ float sh[100];
    __shared__ float sred[8];
    const float EPS = 1.1920929e-07f;
    const float invT = 1.0f / 0.3f;

    for (int l = tid; l < L_; l += 256) {
        slog[l] = g_logits[b * L_ + l];
        sx[l] = x[b * L_ + l];
    }
    __syncthreads();

    float cs0 = 0.f, cs1 = 0.f;
    for (int k = 0; k < KK_; k++) {
        const float* ub = u + (b * KK_ + k) * L_;
        float u0 = ub[tid], u1 = ub[tid + 256];
        u0 = fminf(fmaxf(u0, EPS), 1.0f - EPS);
        u1 = fminf(fmaxf(u1, EPS), 1.0f - EPS);
        float nv0 = (-logf(-logf(u0)) + slog[tid]) * invT;
        float nv1 = (-logf(-logf(u1)) + slog[tid + 256]) * invT;
        float m = bmax256(fmaxf(nv0, nv1), sred);
        float e0 = expf(nv0 - m), e1 = expf(nv1 - m);
        float s = bsum256(e0 + e1, sred);
        float rs = 1.f / s;
        cs0 = fmaxf(cs0, e0 * rs);
        cs1 = fmaxf(cs1, e1 * rs);
    }
    cs_out[b * L_ + tid] = cs0;
    cs_out[b * L_ + tid + 256] = cs1;
    scs[tid] = cs0;
    scs[tid + 256] = cs1;
    __syncthreads();

    // pooling: 2 halves of L across 256 threads
    const int half = tid >> 7, c = tid & 127;
    if (c < 100) {
        float acc = 0.f;
        const int lb_ = half * 256;
        for (int l = lb_; l < lb_ + 256; l += 8) {
            float p[8];
#pragma unroll
            for (int q = 0; q < 8; q++) p[q] = emb[sx[l + q] * 100 + c];
#pragma unroll
            for (int q = 0; q < 8; q++) acc = fmaf(scs[l + q], p[q], acc);
        }
        spool2[half][c] = acc;
    }
    __syncthreads();
    if (tid < 100) {
        float pooled_own = (spool2[0][tid] + spool2[1][tid]) * (1.f / (float)L_);
        spool2[0][tid] = pooled_own;
    }
    __syncthreads();
    if (tid < 100) {
        float a = f1b[tid];
        const float* wr = &f1w[tid * 100];
        for (int e = 0; e < 100; e++) a = fmaf(wr[e], spool2[0][e], a);
        sh[tid] = fmaxf(a, 0.f);
    }
    __syncthreads();
    float hv = (tid < 100) ? hw[tid] * sh[tid] : 0.f;
    hv = bsum256(hv, sred);
    if (tid == 0) out[b] = 1.f / (1.f + expf(-(hv + hb[0])));
}

// ---------------- launch ----------------------------------------------------
extern "C" void kernel_launch(void* const* d_in, const int* in_sizes, int n_in,
                              void* d_out, int out_size) {
    const int*   x   = (const int*)  d_in[0];
    const float* u   = (const float*)d_in[1];
    const float* emb = (const float*)d_in[2];
    const float* c1w = (const float*)d_in[3];
    const float* c1b = (const float*)d_in[4];
    const float* giw = (const float*)d_in[5];
    const float* gib = (const float*)d_in[6];
    const float* c2w = (const float*)d_in[7];
    const float* c2b = (const float*)d_in[8];
    const float* liw = (const float*)d_in[9];
    const float* lib = (const float*)d_in[10];
    const float* c3w = (const float*)d_in[11];
    const float* c3b = (const float*)d_in[12];
    const float* c4w = (const float*)d_in[13];
    const float* c4b = (const float*)d_in[14];
    const float* f1w = (const float*)d_in[15];
    const float* f1b = (const float*)d_in[16];
    const float* hw  = (const float*)d_in[17];
    const float* hb  = (const float*)d_in[18];

    float* out = (float*)d_out;          // [B,1] first
    float* cs  = out + B_;               // then csamples [B,L]

    cudaFuncSetAttribute(kC1, cudaFuncAttributeMaxDynamicSharedMemorySize, C1_SMEM);
    cudaFuncSetAttribute(kCF, cudaFuncAttributeMaxDynamicSharedMemorySize, CF_SMEM);

    k0_prep<<<593, 256>>>(c1w, c2w, liw, c3w);
    kC1<<<dim3(4, B_), 256, C1_SMEM>>>(x, emb, c1b);
    kG<<<B_, 128>>>(giw, gib, c3w, c3b);
    kCF<<<dim3(4, B_), 256, CF_SMEM>>>(c2b, lib, c4w, c4b);
    kS<<<B_, 256>>>(u, x, emb, f1w, f1b, hw, hb, cs, out);
}

// round 15
// speedup vs baseline: 1.0960x; 1.0960x over previous
#include <cuda_runtime.h>
#include <cuda_bf16.h>
#include <math.h>
#include <stdint.h>

#define B_   512
#define L_   512
#define KK_  10

// ---------------- scratch (device globals; no allocations) ----------------
__device__ __align__(16) uint32_t g_h1[B_ * L_ * 56];   // h1 bf16x2 [b][l][112ch]
__device__ float    g_logits[B_ * L_];
__device__ float    g_hpart[B_ * 4 * 128];
__device__ float    g_gz[B_ * 128];
__device__ __align__(16) __nv_bfloat16 g_Wb1[3 * 128 * 120];  // [tap][f][k pad120]
__device__ __align__(16) __nv_bfloat16 g_Wb2[3 * 128 * 120];
__device__ __align__(16) __nv_bfloat16 g_WbL[3 * 128 * 120];
__device__ __align__(16) __nv_bfloat16 g_Wb3[112 * 120];      // conv3 loc half
__device__ __align__(16) __nv_bfloat16 g_embb[100000 * 112];  // bf16 emb, pad 112

// ---------------- K0: weight prep -> padded bf16 blobs ---------------------
__global__ void k0_prep(const float* __restrict__ w1, const float* __restrict__ w2,
                        const float* __restrict__ wl, const float* __restrict__ w3) {
    int id = blockIdx.x * 256 + threadIdx.x;
    if (id >= 151680) return;
    if (id < 138240) {
        int conv = id / 46080, rem = id - conv * 46080;
        int t = rem / 15360, p = rem - t * 15360;
        int f = p / 120, k = p - f * 120;
        float v = 0.f;
        const float* src = (conv == 0) ? w1 : (conv == 1) ? w2 : wl;
        if (f < 100 && k < 100) v = src[f * 300 + k * 3 + t];
        __nv_bfloat16* dst = (conv == 0) ? g_Wb1 : (conv == 1) ? g_Wb2 : g_WbL;
        dst[t * 15360 + f * 120 + k] = __float2bfloat16(v);
    } else {
        int p = id - 138240;
        int f = p / 120, k = p - f * 120;
        float v = 0.f;
        if (f < 100 && k < 100) v = w3[f * 200 + 100 + k];
        g_Wb3[p] = __float2bfloat16(v);
    }
}
// ---------------- K0e: emb fp32 -> bf16 padded table -----------------------
__global__ __launch_bounds__(256) void k0e(const float* __restrict__ emb) {
    int id = blockIdx.x * 256 + threadIdx.x;          // over 100000*56 pairs
    if (id >= 100000 * 56) return;
    int row = id / 56, c = id - row * 56;
    uint32_t pk = 0;
    if (c < 50) {
        float2 v = ((const float2*)emb)[row * 50 + c];
        __nv_bfloat162 h = __floats2bfloat162_rn(v.x, v.y);
        pk = *(uint32_t*)&h;
    }
    ((uint32_t*)g_embb)[row * 56 + c] = pk;
}

// ---------------- PTX primitives -------------------------------------------
__device__ __forceinline__ uint32_t smem_u32(const void* p) {
    uint32_t a;
    asm("{ .reg .u64 t; cvta.to.shared.u64 t, %1; cvt.u32.u64 %0, t; }" : "=r"(a) : "l"(p));
    return a;
}
__device__ __forceinline__ void ldsm_x4(uint32_t& a0, uint32_t& a1, uint32_t& a2,
                                        uint32_t& a3, uint32_t addr) {
    asm volatile("ldmatrix.sync.aligned.m8n8.x4.shared.b16 {%0,%1,%2,%3}, [%4];"
                 : "=r"(a0), "=r"(a1), "=r"(a2), "=r"(a3) : "r"(addr));
}
__device__ __forceinline__ void ldsm_x2(uint32_t& b0, uint32_t& b1, uint32_t addr) {
    asm volatile("ldmatrix.sync.aligned.m8n8.x2.shared.b16 {%0,%1}, [%2];"
                 : "=r"(b0), "=r"(b1) : "r"(addr));
}
__device__ __forceinline__ void mma16816(float* d, uint32_t a0, uint32_t a1,
                                         uint32_t a2, uint32_t a3,
                                         uint32_t b0, uint32_t b1) {
    asm volatile("mma.sync.aligned.m16n8k16.row.col.f32.bf16.bf16.f32 "
                 "{%0,%1,%2,%3},{%4,%5,%6,%7},{%8,%9},{%0,%1,%2,%3};"
                 : "+f"(d[0]), "+f"(d[1]), "+f"(d[2]), "+f"(d[3])
                 : "r"(a0), "r"(a1), "r"(a2), "r"(a3), "r"(b0), "r"(b1));
}
__device__ __forceinline__ float2 bf2f(uint32_t u) {
    __nv_bfloat162 h = *(__nv_bfloat162*)&u;
    return make_float2(__bfloat162float(h.x), __bfloat162float(h.y));
}
__device__ __forceinline__ void cpa16(uint32_t d, const void* s) {
    asm volatile("cp.async.cg.shared.global [%0], [%1], 16;" :: "r"(d), "l"(s));
}
__device__ __forceinline__ void cpa16z(uint32_t d, const void* s, int sz) {
    asm volatile("cp.async.cg.shared.global [%0], [%1], 16, %2;" :: "r"(d), "l"(s), "r"(sz));
}
__device__ __forceinline__ void cpa_commit() {
    asm volatile("cp.async.commit_group;" ::: "memory");
}
__device__ __forceinline__ void cpa_wait0() {
    asm volatile("cp.async.wait_group 0;" ::: "memory");
}

// ---------------- single-tap conv GEMM (proven core) -----------------------
__device__ __forceinline__ void gemm_tap(uint32_t sData_u, uint32_t wb_u,
                                         float (&d)[2][7][4], int rshift,
                                         int lane, int wf, int wl) {
    const int lam = lane & 15;
#pragma unroll
    for (int ks = 0; ks < 7; ks++) {
        uint32_t b0[7], b1[7];
#pragma unroll
        for (int nf = 0; nf < 7; nf++) {
            uint32_t addr = wb_u + (uint32_t)(wf * 56 + nf * 8 + (lam & 7)) * 240
                          + ks * 32 + ((lam >> 3) & 1) * 16;
            ldsm_x2(b0[nf], b1[nf], addr);
        }
#pragma unroll
        for (int mi = 0; mi < 2; mi++) {
            uint32_t addr = sData_u + (uint32_t)(wl * 32 + mi * 16 + rshift + lam) * 240
                          + ks * 32 + (lane >> 4) * 16;
            uint32_t a0, a1, a2, a3;
            ldsm_x4(a0, a1, a2, a3, addr);
#pragma unroll
            for (int nf = 0; nf < 7; nf++)
                mma16816(d[mi][nf], a0, a1, a2, a3, b0[nf], b1[nf]);
        }
    }
}
#define ZERO_D(dd) do {                                                        \
    _Pragma("unroll") for (int mi = 0; mi < 2; mi++)                           \
    _Pragma("unroll") for (int nf = 0; nf < 7; nf++)                           \
    _Pragma("unroll") for (int q = 0; q < 4; q++) (dd)[mi][nf][q] = 0.f;       \
} while (0)

// staging source for kCF pipeline step s (0..6): conv2 taps, li taps, w3
__device__ __forceinline__ const uint4* wsrc(int s) {
    if (s < 3) return ((const uint4*)g_Wb2) + s * 1920;
    if (s < 6) return ((const uint4*)g_WbL) + (s - 3) * 1920;
    return (const uint4*)g_Wb3;
}
__device__ __forceinline__ void stage_w(uint32_t dst_u, const uint4* src, int tid) {
    for (int i = tid; i < 1680; i += 256) cpa16(dst_u + i * 16, src + i);
    cpa_commit();
}

// ---------------- KC1: emb gather (cp.async bf16) + conv1 -> h1 + hmean ----
#define C1_W    31200
#define C1_BIAS 111840
#define C1_HS   112352
#define C1_SMEM 112800
__global__ __launch_bounds__(256, 2) void kC1(const int* __restrict__ x,
                                              const float* __restrict__ b1) {
    extern __shared__ char sm[];
    uint32_t* sD32 = (uint32_t*)sm;
    float* sBias = (float*)(sm + C1_BIAS);
    float* sHs = (float*)(sm + C1_HS);
    const int cx = blockIdx.x, b = blockIdx.y, tid = threadIdx.x;
    const int lane = tid & 31, wid = tid >> 5, wf = wid & 1, wl = wid >> 1;
    const int l0 = cx * 128;
    const int* xb = x + b * L_;
    const uint32_t sData_u = smem_u32(sm), sW_u = sData_u + C1_W;

    // weights + emb rows, all via cp.async (single wait)
    {
        const uint4* ws = (const uint4*)g_Wb1;
        for (int i = tid; i < 5040; i += 256) {
            int t = i / 1680, r = i - t * 1680;
            cpa16(sW_u + (t * 1680 + r) * 16, ws + t * 1920 + r);
        }
    }
    for (int idx = tid; idx < 130 * 14; idx += 256) {
        int r = idx / 14, q = idx - r * 14;
        int l = l0 - 1 + r;
        bool ok = (unsigned)l < (unsigned)L_;
        int tok = ok ? xb[l] : 0;
        const uint4* s = ((const uint4*)(g_embb + (size_t)tok * 112)) + q;
        cpa16z(sData_u + (uint32_t)r * 240 + q * 16, s, ok ? 16 : 0);
    }
    cpa_commit();
    if (tid < 128) sBias[tid] = (tid < 100) ? b1[tid] : 0.f;
    if (tid < 112) sHs[tid] = 0.f;
    cpa_wait0();
    __syncthreads();

    float d[2][7][4];
    ZERO_D(d);
    gemm_tap(sData_u, sW_u, d, 0, lane, wf, wl);
    gemm_tap(sData_u, sW_u + 26880, d, 1, lane, wf, wl);
    gemm_tap(sData_u, sW_u + 53760, d, 2, lane, wf, wl);
    __syncthreads();                     // all data-region reads complete

    const int lq = lane >> 2, fq = lane & 3;
    float acc[7][2];
#pragma unroll
    for (int nf = 0; nf < 7; nf++) { acc[nf][0] = 0.f; acc[nf][1] = 0.f; }
#pragma unroll
    for (int mi = 0; mi < 2; mi++) {
        int lr = wl * 32 + mi * 16 + lq;
#pragma unroll
        for (int nf = 0; nf < 7; nf++) {
            int fp = wf * 28 + nf * 4 + fq;
            float bx = sBias[2 * fp], by = sBias[2 * fp + 1];
            float v0 = fmaxf(d[mi][nf][0] + bx, 0.f), v1 = fmaxf(d[mi][nf][1] + by, 0.f);
            float v2 = fmaxf(d[mi][nf][2] + bx, 0.f), v3 = fmaxf(d[mi][nf][3] + by, 0.f);
            __nv_bfloat162 p0 = __floats2bfloat162_rn(v0, v1);
            __nv_bfloat162 p1 = __floats2bfloat162_rn(v2, v3);
            sD32[lr * 60 + fp] = *(uint32_t*)&p0;
            sD32[(lr + 8) * 60 + fp] = *(uint32_t*)&p1;
            acc[nf][0] += v0 + v2;
            acc[nf][1] += v1 + v3;
        }
    }
#pragma unroll
    for (int nf = 0; nf < 7; nf++)
#pragma unroll
        for (int j = 0; j < 2; j++) {
            float v = acc[nf][j];
            v += __shfl_xor_sync(0xffffffffu, v, 4);
            v += __shfl_xor_sync(0xffffffffu, v, 8);
            v += __shfl_xor_sync(0xffffffffu, v, 16);
            if (lane < 4) atomicAdd(&sHs[wf * 56 + nf * 8 + fq * 2 + j], v);
        }
    __syncthreads();
    {
        uint4* dst4 = (uint4*)(g_h1 + ((size_t)b * L_ + l0) * 56);
        const uint4* src4 = (const uint4*)sD32;
        for (int idx = tid; idx < 128 * 14; idx += 256) {
            int row = idx / 14, q = idx - row * 14;
            dst4[row * 14 + q] = src4[row * 15 + q];
        }
    }
    if (tid < 112) g_hpart[(b * 4 + cx) * 128 + tid] = sHs[tid];
}

// ---------------- KG: hmean -> g -> gz -------------------------------------
__global__ __launch_bounds__(128) void kG(const float* __restrict__ giw,
                                          const float* __restrict__ gib,
                                          const float* __restrict__ c3w,
                                          const float* __restrict__ c3b) {
    const int b = blockIdx.x, tid = threadIdx.x;
    __shared__ float shm[100], sg[100];
    if (tid < 100) {
        const float* p = g_hpart + b * 4 * 128 + tid;
        shm[tid] = (p[0] + p[128] + p[256] + p[384]) * (1.f / (float)L_);
    }
    __syncthreads();
    if (tid < 100) {
        float a = gib[tid];
        const float* wr = &giw[tid * 100];
        for (int f = 0; f < 100; f++) a = fmaf(wr[f], shm[f], a);
        sg[tid] = fmaxf(a, 0.f);
    }
    __syncthreads();
    if (tid < 100) {
        float a = c3b[tid];
        const float* wr = &c3w[tid * 200];
        for (int h = 0; h < 100; h++) a = fmaf(wr[h], sg[h], a);
        g_gz[b * 128 + tid] = a;
    }
}

// ---------------- KCF: fused conv2 -> li -> conv3 -> logits (R12 proven) ---
#define CF_WA   31680
#define CF_WB   58560
#define CF_B2   85440
#define CF_BL   85952
#define CF_GZ   86464
#define CF_C4   86976
#define CF_LOG  87488
#define CF_SMEM 88000
__global__ __launch_bounds__(256, 2) void kCF(const float* __restrict__ b2,
                                              const float* __restrict__ lb,
                                              const float* __restrict__ c4w,
                                              const float* __restrict__ c4b) {
    extern __shared__ char sm[];
    uint32_t* sD32 = (uint32_t*)sm;                 // D1, then H2, then Loc
    __nv_bfloat16* sD16 = (__nv_bfloat16*)sm;
    float* sB2 = (float*)(sm + CF_B2);
    float* sBL = (float*)(sm + CF_BL);
    float* sGz = (float*)(sm + CF_GZ);
    float* sC4 = (float*)(sm + CF_C4);
    float* sLog = (float*)(sm + CF_LOG);
    const int cx = blockIdx.x, b = blockIdx.y, tid = threadIdx.x;
    const int lane = tid & 31, wid = tid >> 5, wf = wid & 1, wl = wid >> 1;
    const int l0 = cx * 128;
    const uint4* src = (const uint4*)(g_h1 + (size_t)b * L_ * 56);
    const uint32_t sD_u = smem_u32(sm);
    uint32_t wcur = sD_u + CF_WA, wnext = sD_u + CF_WB;

    stage_w(wcur, wsrc(0), tid);
    for (int idx = tid; idx < 132 * 15; idx += 256) {
        int r = idx / 15, q = idx - r * 15;
        int l = l0 - 2 + r;
        bool ok = (q < 14) && ((unsigned)l < (unsigned)L_);
        const void* s = ok ? (const void*)(src + (size_t)l * 14 + q) : (const void*)src;
        cpa16z(sD_u + (uint32_t)idx * 16, s, ok ? 16 : 0);
    }
    cpa_commit();
    if (tid < 128) {
        sB2[tid] = (tid < 100) ? b2[tid] : 0.f;
        sBL[tid] = (tid < 100) ? lb[tid] : 0.f;
        sGz[tid] = (tid < 100) ? g_gz[b * 128 + tid] : 0.f;
        sC4[tid] = (tid < 100) ? c4w[tid] : 0.f;
        sLog[tid] = 0.f;
    }
    cpa_wait0();
    __syncthreads();

    const int lq = lane >> 2, fq = lane & 3;
    const int hcol = tid / 112, hch = tid - hcol * 112;
    const bool hok = (tid < 224) &&
        ((hcol == 0) ? (l0 - 1 >= 0) : (l0 + 128 < L_));
    float hs = 0.f;

    float d[2][7][4];
    ZERO_D(d);
    // ---- conv2: 3 taps, next weights prefetched during gemm ----
    for (int t = 0; t < 3; t++) {
        stage_w(wnext, wsrc(t + 1), tid);
        gemm_tap(sD_u, wcur, d, 1 + t, lane, wf, wl);
        if (hok) {
            const uint32_t* dr = sD32 + ((hcol ? 129 : 0) + t) * 60;
            const uint4* wr4 = (const uint4*)(g_Wb2 + t * 15360 + hch * 120);
#pragma unroll
            for (int q = 0; q < 13; q++) {
                uint4 w = wr4[q];
                float2 w0 = bf2f(w.x), w1 = bf2f(w.y), w2_ = bf2f(w.z), w3_ = bf2f(w.w);
                float2 a0 = bf2f(dr[4 * q]), a1 = bf2f(dr[4 * q + 1]);
                float2 a2 = bf2f(dr[4 * q + 2]), a3 = bf2f(dr[4 * q + 3]);
                hs += a0.x * w0.x + a0.y * w0.y + a1.x * w1.x + a1.y * w1.y
                    + a2.x * w2_.x + a2.y * w2_.y + a3.x * w3_.x + a3.y * w3_.y;
            }
        }
        cpa_wait0();
        __syncthreads();
        uint32_t tmp = wcur; wcur = wnext; wnext = tmp;
    }
    // ---- conv2 epilogue: H2 overwrites D1 region (rows 0..129) ----
#pragma unroll
    for (int mi = 0; mi < 2; mi++) {
        int lr = wl * 32 + mi * 16 + lq;
#pragma unroll
        for (int nf = 0; nf < 7; nf++) {
            int fp = wf * 28 + nf * 4 + fq;
            float bx = sB2[2 * fp], by = sB2[2 * fp + 1];
            float v0 = fmaxf(d[mi][nf][0] + bx, 0.f), v1 = fmaxf(d[mi][nf][1] + by, 0.f);
            float v2 = fmaxf(d[mi][nf][2] + bx, 0.f), v3 = fmaxf(d[mi][nf][3] + by, 0.f);
            __nv_bfloat162 p0 = __floats2bfloat162_rn(v0, v1);
            __nv_bfloat162 p1 = __floats2bfloat162_rn(v2, v3);
            sD32[(lr + 1) * 60 + fp] = *(uint32_t*)&p0;
            sD32[(lr + 9) * 60 + fp] = *(uint32_t*)&p1;
        }
    }
    if (tid < 224) {
        float v = hok ? fmaxf(hs + sB2[hch], 0.f) : 0.f;
        sD16[(hcol ? 129 : 0) * 120 + hch] = __float2bfloat16(v);
    }
    __syncthreads();

    // ---- li: 3 taps over H2, prefetch li t+1 / w3 ----
    ZERO_D(d);
    for (int t = 0; t < 3; t++) {
        if (t < 2) stage_w(wnext, wsrc(t + 4), tid);
        else stage_w(wnext, wsrc(6), tid);
        gemm_tap(sD_u, wcur, d, t, lane, wf, wl);
        cpa_wait0();
        __syncthreads();
        uint32_t tmp = wcur; wcur = wnext; wnext = tmp;
    }
    // ---- Loc = relu(D + lb) -> DH rows 0..127 ----
#pragma unroll
    for (int mi = 0; mi < 2; mi++) {
        int lr = wl * 32 + mi * 16 + lq;
#pragma unroll
        for (int nf = 0; nf < 7; nf++) {
            int fp = wf * 28 + nf * 4 + fq;
            float bx = sBL[2 * fp], by = sBL[2 * fp + 1];
            float v0 = fmaxf(d[mi][nf][0] + bx, 0.f), v1 = fmaxf(d[mi][nf][1] + by, 0.f);
            float v2 = fmaxf(d[mi][nf][2] + bx, 0.f), v3 = fmaxf(d[mi][nf][3] + by, 0.f);
            __nv_bfloat162 p0 = __floats2bfloat162_rn(v0, v1);
            __nv_bfloat162 p1 = __floats2bfloat162_rn(v2, v3);
            sD32[lr * 60 + fp] = *(uint32_t*)&p0;
            sD32[(lr + 8) * 60 + fp] = *(uint32_t*)&p1;
        }
    }
    __syncthreads();

    // ---- conv3 loc half + fused conv4 -> logits ----
    ZERO_D(d);
    gemm_tap(sD_u, wcur, d, 0, lane, wf, wl);
#pragma unroll
    for (int mi = 0; mi < 2; mi++) {
        int lr = wl * 32 + mi * 16 + lq;
        float pA = 0.f, pB = 0.f;
#pragma unroll
        for (int nf = 0; nf < 7; nf++) {
            int f0 = wf * 56 + nf * 8 + fq * 2;
            float g0 = sGz[f0], g1 = sGz[f0 + 1];
            float c0 = sC4[f0], c1 = sC4[f0 + 1];
            pA += c0 * fmaxf(d[mi][nf][0] + g0, 0.f) + c1 * fmaxf(d[mi][nf][1] + g1, 0.f);
            pB += c0 * fmaxf(d[mi][nf][2] + g0, 0.f) + c1 * fmaxf(d[mi][nf][3] + g1, 0.f);
        }
        pA += __shfl_xor_sync(0xffffffffu, pA, 1);
        pA += __shfl_xor_sync(0xffffffffu, pA, 2);
        pB += __shfl_xor_sync(0xffffffffu, pB, 1);
        pB += __shfl_xor_sync(0xffffffffu, pB, 2);
        if (fq == 0) {
            atomicAdd(&sLog[lr], pA);
            atomicAdd(&sLog[lr + 8], pB);
        }
    }
    __syncthreads();
    if (tid < 128) g_logits[b * L_ + l0 + tid] = sLog[tid] + c4b[0];
}

// ---------------- block reductions (256 threads) ---------------------------
__device__ __forceinline__ float bmax256(float v, float* sred) {
#pragma unroll
    for (int o = 16; o > 0; o >>= 1) v = fmaxf(v, __shfl_xor_sync(0xffffffffu, v, o));
    int w = threadIdx.x >> 5;
    if ((threadIdx.x & 31) == 0) sred[w] = v;
    __syncthreads();
    if (threadIdx.x == 0) {
        float t = sred[0];
#pragma unroll
        for (int i = 1; i < 8; i++) t = fmaxf(t, sred[i]);
        sred[0] = t;
    }
    __syncthreads();
    float r = sred[0];
    __syncthreads();
    return r;
}
__device__ __forceinline__ float bsum256(float v, float* sred) {
#pragma unroll
    for (int o = 16; o > 0; o >>= 1) v += __shfl_xor_sync(0xffffffffu, v, o);
    int w = threadIdx.x >> 5;
    if ((threadIdx.x & 31) == 0) sred[w] = v;
    __syncthreads();
    if (threadIdx.x == 0) {
        float t = sred[0];
#pragma unroll
        for (int i = 1; i < 8; i++) t += sred[i];
        sred[0] = t;
    }
    __syncthreads();
    float r = sred[0];
    __syncthreads();
    return r;
}

// ---------------- KS: gumbel softmax + pooling + MLP + sigmoid (fused) -----
__global__ __launch_bounds__(256) void kS(const float* __restrict__ u,
                                          const int* __restrict__ x,
                                          const float* __restrict__ emb,
                                          const float* __restrict__ f1w,
                                          const float* __restrict__ f1b,
                                          const float* __restrict__ hw,
                                          const float* __restrict__ hb,
                                          float* __restrict__ cs_out,
                                          float* __restrict__ out) {
    const int b = blockIdx.x, tid = threadIdx.x;
    __shared__ float slog[L_];
    __shared__ float scs[L_];
    __shared__ int sx[L_];
    __shared__ float spool2[2][128];
    __shared__ float sh[100];
    __shared__ float sred[8];
    const float EPS = 1.1920929e-07f;
    const float invT = 1.0f / 0.3f;

    for (int l = tid; l < L_; l += 256) {
        slog[l] = g_logits[b * L_ + l];
        sx[l] = x[b * L_ + l];
    }
    __syncthreads();

    float cs0 = 0.f, cs1 = 0.f;
    for (int k = 0; k < KK_; k++) {
        const float* ub = u + (b * KK_ + k) * L_;
        float u0 = ub[tid], u1 = ub[tid + 256];
        u0 = fminf(fmaxf(u0, EPS), 1.0f - EPS);
        u1 = fminf(fmaxf(u1, EPS), 1.0f - EPS);
        float nv0 = (-logf(-logf(u0)) + slog[tid]) * invT;
        float nv1 = (-logf(-logf(u1)) + slog[tid + 256]) * invT;
        float m = bmax256(fmaxf(nv0, nv1), sred);
        float e0 = expf(nv0 - m), e1 = expf(nv1 - m);
        float s = bsum256(e0 + e1, sred);
        float rs = 1.f / s;
        cs0 = fmaxf(cs0, e0 * rs);
        cs1 = fmaxf(cs1, e1 * rs);
    }
    cs_out[b * L_ + tid] = cs0;
    cs_out[b * L_ + tid + 256] = cs1;
    scs[tid] = cs0;
    scs[tid + 256] = cs1;
    __syncthreads();

    const int half = tid >> 7, c = tid & 127;
    if (c < 100) {
        float acc = 0.f;
        const int lb_ = half * 256;
        for (int l = lb_; l < lb_ + 256; l += 8) {
            float p[8];
#pragma unroll
            for (int q = 0; q < 8; q++) p[q] = emb[sx[l + q] * 100 + c];
#pragma unroll
            for (int q = 0; q < 8; q++) acc = fmaf(scs[l + q], p[q], acc);
        }
        spool2[half][c] = acc;
    }
    __syncthreads();
    if (tid < 100) {
        float pooled_own = (spool2[0][tid] + spool2[1][tid]) * (1.f / (float)L_);
        spool2[0][tid] = pooled_own;
    }
    __syncthreads();
    if (tid < 100) {
        float a = f1b[tid];
        const float* wr = &f1w[tid * 100];
        for (int e = 0; e < 100; e++) a = fmaf(wr[e], spool2[0][e], a);
        sh[tid] = fmaxf(a, 0.f);
    }
    __syncthreads();
    float hv = (tid < 100) ? hw[tid] * sh[tid] : 0.f;
    hv = bsum256(hv, sred);
    if (tid == 0) out[b] = 1.f / (1.f + expf(-(hv + hb[0])));
}

// ---------------- launch ----------------------------------------------------
extern "C" void kernel_launch(void* const* d_in, const int* in_sizes, int n_in,
                              void* d_out, int out_size) {
    const int*   x   = (const int*)  d_in[0];
    const float* u   = (const float*)d_in[1];
    const float* emb = (const float*)d_in[2];
    const float* c1w = (const float*)d_in[3];
    const float* c1b = (const float*)d_in[4];
    const float* giw = (const float*)d_in[5];
    const float* gib = (const float*)d_in[6];
    const float* c2w = (const float*)d_in[7];
    const float* c2b = (const float*)d_in[8];
    const float* liw = (const float*)d_in[9];
    const float* lib = (const float*)d_in[10];
    const float* c3w = (const float*)d_in[11];
    const float* c3b = (const float*)d_in[12];
    const float* c4w = (const float*)d_in[13];
    const float* c4b = (const float*)d_in[14];
    const float* f1w = (const float*)d_in[15];
    const float* f1b = (const float*)d_in[16];
    const float* hw  = (const float*)d_in[17];
    const float* hb  = (const float*)d_in[18];

    float* out = (float*)d_out;          // [B,1] first
    float* cs  = out + B_;               // then csamples [B,L]

    cudaFuncSetAttribute(kC1, cudaFuncAttributeMaxDynamicSharedMemorySize, C1_SMEM);
    cudaFuncSetAttribute(kCF, cudaFuncAttributeMaxDynamicSharedMemorySize, CF_SMEM);

    k0_prep<<<593, 256>>>(c1w, c2w, liw, c3w);
    k0e<<<(100000 * 56 + 255) / 256, 256>>>(emb);
    kC1<<<dim3(4, B_), 256, C1_SMEM>>>(x, c1b);
    kG<<<B_, 128>>>(giw, gib, c3w, c3b);
    kCF<<<dim3(4, B_), 256, CF_SMEM>>>(c2b, lib, c4w, c4b);
    kS<<<B_, 256>>>(u, x, emb, f1w, f1b, hw, hb, cs, out);
}

// round 16
// speedup vs baseline: 1.1906x; 1.0863x over previous
#include <cuda_runtime.h>
#include <cuda_bf16.h>
#include <math.h>
#include <stdint.h>

#define B_   512
#define L_   512
#define KK_  10

// ---------------- scratch (device globals; no allocations) ----------------
__device__ __align__(16) uint32_t g_h1[B_ * L_ * 56];   // h1 bf16x2 [b][l][112ch]
__device__ float    g_logits[B_ * L_];
__device__ float    g_hpart[B_ * 4 * 128];
__device__ float    g_gz[B_ * 128];
__device__ __align__(16) __nv_bfloat16 g_Wb1[3 * 128 * 120];  // [tap][f][k pad120]
__device__ __align__(16) __nv_bfloat16 g_Wb2[3 * 128 * 120];
__device__ __align__(16) __nv_bfloat16 g_WbL[3 * 128 * 120];
__device__ __align__(16) __nv_bfloat16 g_Wb3[112 * 120];      // conv3 loc half
__device__ __align__(16) __nv_bfloat16 g_embb[100000 * 112];  // bf16 emb, pad 112

// ---------------- K0: weight prep -> padded bf16 blobs ---------------------
__global__ void k0_prep(const float* __restrict__ w1, const float* __restrict__ w2,
                        const float* __restrict__ wl, const float* __restrict__ w3) {
    int id = blockIdx.x * 256 + threadIdx.x;
    if (id >= 151680) return;
    if (id < 138240) {
        int conv = id / 46080, rem = id - conv * 46080;
        int t = rem / 15360, p = rem - t * 15360;
        int f = p / 120, k = p - f * 120;
        float v = 0.f;
        const float* src = (conv == 0) ? w1 : (conv == 1) ? w2 : wl;
        if (f < 100 && k < 100) v = src[f * 300 + k * 3 + t];
        __nv_bfloat16* dst = (conv == 0) ? g_Wb1 : (conv == 1) ? g_Wb2 : g_WbL;
        dst[t * 15360 + f * 120 + k] = __float2bfloat16(v);
    } else {
        int p = id - 138240;
        int f = p / 120, k = p - f * 120;
        float v = 0.f;
        if (f < 100 && k < 100) v = w3[f * 200 + 100 + k];
        g_Wb3[p] = __float2bfloat16(v);
    }
}
// ---------------- K0e: emb fp32 -> bf16 padded table -----------------------
__global__ __launch_bounds__(256) void k0e(const float* __restrict__ emb) {
    int id = blockIdx.x * 256 + threadIdx.x;          // over 100000*56 pairs
    if (id >= 100000 * 56) return;
    int row = id / 56, c = id - row * 56;
    uint32_t pk = 0;
    if (c < 50) {
        float2 v = ((const float2*)emb)[row * 50 + c];
        __nv_bfloat162 h = __floats2bfloat162_rn(v.x, v.y);
        pk = *(uint32_t*)&h;
    }
    ((uint32_t*)g_embb)[row * 56 + c] = pk;
}

// ---------------- PTX primitives -------------------------------------------
__device__ __forceinline__ uint32_t smem_u32(const void* p) {
    uint32_t a;
    asm("{ .reg .u64 t; cvta.to.shared.u64 t, %1; cvt.u32.u64 %0, t; }" : "=r"(a) : "l"(p));
    return a;
}
__device__ __forceinline__ void ldsm_x4(uint32_t& a0, uint32_t& a1, uint32_t& a2,
                                        uint32_t& a3, uint32_t addr) {
    asm volatile("ldmatrix.sync.aligned.m8n8.x4.shared.b16 {%0,%1,%2,%3}, [%4];"
                 : "=r"(a0), "=r"(a1), "=r"(a2), "=r"(a3) : "r"(addr));
}
__device__ __forceinline__ void ldsm_x2(uint32_t& b0, uint32_t& b1, uint32_t addr) {
    asm volatile("ldmatrix.sync.aligned.m8n8.x2.shared.b16 {%0,%1}, [%2];"
                 : "=r"(b0), "=r"(b1) : "r"(addr));
}
__device__ __forceinline__ void mma16816(float* d, uint32_t a0, uint32_t a1,
                                         uint32_t a2, uint32_t a3,
                                         uint32_t b0, uint32_t b1) {
    asm volatile("mma.sync.aligned.m16n8k16.row.col.f32.bf16.bf16.f32 "
                 "{%0,%1,%2,%3},{%4,%5,%6,%7},{%8,%9},{%0,%1,%2,%3};"
                 : "+f"(d[0]), "+f"(d[1]), "+f"(d[2]), "+f"(d[3])
                 : "r"(a0), "r"(a1), "r"(a2), "r"(a3), "r"(b0), "r"(b1));
}
__device__ __forceinline__ float2 bf2f(uint32_t u) {
    __nv_bfloat162 h = *(__nv_bfloat162*)&u;
    return make_float2(__bfloat162float(h.x), __bfloat162float(h.y));
}
__device__ __forceinline__ void cpa16(uint32_t d, const void* s) {
    asm volatile("cp.async.cg.shared.global [%0], [%1], 16;" :: "r"(d), "l"(s));
}
__device__ __forceinline__ void cpa16z(uint32_t d, const void* s, int sz) {
    asm volatile("cp.async.cg.shared.global [%0], [%1], 16, %2;" :: "r"(d), "l"(s), "r"(sz));
}
__device__ __forceinline__ void cpa_commit() {
    asm volatile("cp.async.commit_group;" ::: "memory");
}
__device__ __forceinline__ void cpa_wait0() {
    asm volatile("cp.async.wait_group 0;" ::: "memory");
}

// ---------------- single-tap conv GEMM (proven core) -----------------------
__device__ __forceinline__ void gemm_tap(uint32_t sData_u, uint32_t wb_u,
                                         float (&d)[2][7][4], int rshift,
                                         int lane, int wf, int wl) {
    const int lam = lane & 15;
#pragma unroll
    for (int ks = 0; ks < 7; ks++) {
        uint32_t b0[7], b1[7];
#pragma unroll
        for (int nf = 0; nf < 7; nf++) {
            uint32_t addr = wb_u + (uint32_t)(wf * 56 + nf * 8 + (lam & 7)) * 240
                          + ks * 32 + ((lam >> 3) & 1) * 16;
            ldsm_x2(b0[nf], b1[nf], addr);
        }
#pragma unroll
        for (int mi = 0; mi < 2; mi++) {
            uint32_t addr = sData_u + (uint32_t)(wl * 32 + mi * 16 + rshift + lam) * 240
                          + ks * 32 + (lane >> 4) * 16;
            uint32_t a0, a1, a2, a3;
            ldsm_x4(a0, a1, a2, a3, addr);
#pragma unroll
            for (int nf = 0; nf < 7; nf++)
                mma16816(d[mi][nf], a0, a1, a2, a3, b0[nf], b1[nf]);
        }
    }
}
#define ZERO_D(dd) do {                                                        \
    _Pragma("unroll") for (int mi = 0; mi < 2; mi++)                           \
    _Pragma("unroll") for (int nf = 0; nf < 7; nf++)                           \
    _Pragma("unroll") for (int q = 0; q < 4; q++) (dd)[mi][nf][q] = 0.f;       \
} while (0)

// staging source for kCF pipeline step s (0..6): conv2 taps, li taps, w3
__device__ __forceinline__ const uint4* wsrc(int s) {
    if (s < 3) return ((const uint4*)g_Wb2) + s * 1920;
    if (s < 6) return ((const uint4*)g_WbL) + (s - 3) * 1920;
    return (const uint4*)g_Wb3;
}
__device__ __forceinline__ void stage_w(uint32_t dst_u, const uint4* src, int tid) {
    for (int i = tid; i < 1680; i += 256) cpa16(dst_u + i * 16, src + i);
    cpa_commit();
}

// ---------------- KC1: emb gather (cp.async bf16) + conv1 -> h1 + hmean ----
#define C1_W    31200
#define C1_BIAS 111840
#define C1_HS   112352
#define C1_SMEM 112800
__global__ __launch_bounds__(256, 2) void kC1(const int* __restrict__ x,
                                              const float* __restrict__ b1) {
    extern __shared__ char sm[];
    uint32_t* sD32 = (uint32_t*)sm;
    float* sBias = (float*)(sm + C1_BIAS);
    float* sHs = (float*)(sm + C1_HS);
    const int cx = blockIdx.x, b = blockIdx.y, tid = threadIdx.x;
    const int lane = tid & 31, wid = tid >> 5, wf = wid & 1, wl = wid >> 1;
    const int l0 = cx * 128;
    const int* xb = x + b * L_;
    const uint32_t sData_u = smem_u32(sm), sW_u = sData_u + C1_W;

    {
        const uint4* ws = (const uint4*)g_Wb1;
        for (int i = tid; i < 5040; i += 256) {
            int t = i / 1680, r = i - t * 1680;
            cpa16(sW_u + (t * 1680 + r) * 16, ws + t * 1920 + r);
        }
    }
    for (int idx = tid; idx < 130 * 14; idx += 256) {
        int r = idx / 14, q = idx - r * 14;
        int l = l0 - 1 + r;
        bool ok = (unsigned)l < (unsigned)L_;
        int tok = ok ? xb[l] : 0;
        const uint4* s = ((const uint4*)(g_embb + (size_t)tok * 112)) + q;
        cpa16z(sData_u + (uint32_t)r * 240 + q * 16, s, ok ? 16 : 0);
    }
    cpa_commit();
    if (tid < 128) sBias[tid] = (tid < 100) ? b1[tid] : 0.f;
    if (tid < 112) sHs[tid] = 0.f;
    cpa_wait0();
    __syncthreads();

    float d[2][7][4];
    ZERO_D(d);
    gemm_tap(sData_u, sW_u, d, 0, lane, wf, wl);
    gemm_tap(sData_u, sW_u + 26880, d, 1, lane, wf, wl);
    gemm_tap(sData_u, sW_u + 53760, d, 2, lane, wf, wl);
    __syncthreads();

    const int lq = lane >> 2, fq = lane & 3;
    float acc[7][2];
#pragma unroll
    for (int nf = 0; nf < 7; nf++) { acc[nf][0] = 0.f; acc[nf][1] = 0.f; }
#pragma unroll
    for (int mi = 0; mi < 2; mi++) {
        int lr = wl * 32 + mi * 16 + lq;
#pragma unroll
        for (int nf = 0; nf < 7; nf++) {
            int fp = wf * 28 + nf * 4 + fq;
            float bx = sBias[2 * fp], by = sBias[2 * fp + 1];
            float v0 = fmaxf(d[mi][nf][0] + bx, 0.f), v1 = fmaxf(d[mi][nf][1] + by, 0.f);
            float v2 = fmaxf(d[mi][nf][2] + bx, 0.f), v3 = fmaxf(d[mi][nf][3] + by, 0.f);
            __nv_bfloat162 p0 = __floats2bfloat162_rn(v0, v1);
            __nv_bfloat162 p1 = __floats2bfloat162_rn(v2, v3);
            sD32[lr * 60 + fp] = *(uint32_t*)&p0;
            sD32[(lr + 8) * 60 + fp] = *(uint32_t*)&p1;
            acc[nf][0] += v0 + v2;
            acc[nf][1] += v1 + v3;
        }
    }
#pragma unroll
    for (int nf = 0; nf < 7; nf++)
#pragma unroll
        for (int j = 0; j < 2; j++) {
            float v = acc[nf][j];
            v += __shfl_xor_sync(0xffffffffu, v, 4);
            v += __shfl_xor_sync(0xffffffffu, v, 8);
            v += __shfl_xor_sync(0xffffffffu, v, 16);
            if (lane < 4) atomicAdd(&sHs[wf * 56 + nf * 8 + fq * 2 + j], v);
        }
    __syncthreads();
    {
        uint4* dst4 = (uint4*)(g_h1 + ((size_t)b * L_ + l0) * 56);
        const uint4* src4 = (const uint4*)sD32;
        for (int idx = tid; idx < 128 * 14; idx += 256) {
            int row = idx / 14, q = idx - row * 14;
            dst4[row * 14 + q] = src4[row * 15 + q];
        }
    }
    if (tid < 112) g_hpart[(b * 4 + cx) * 128 + tid] = sHs[tid];
}

// ---------------- KG: hmean -> g -> gz (512 thr, split-4 dots) -------------
__global__ __launch_bounds__(512) void kG(const float* __restrict__ giw,
                                          const float* __restrict__ gib,
                                          const float* __restrict__ c3w,
                                          const float* __restrict__ c3b) {
    const int b = blockIdx.x, tid = threadIdx.x;
    __shared__ float shm[100], sg[100];
    if (tid < 100) {
        const float* p = g_hpart + b * 4 * 128 + tid;
        shm[tid] = (p[0] + p[128] + p[256] + p[384]) * (1.f / (float)L_);
    }
    __syncthreads();
    const int f = tid >> 2, part = tid & 3;
    {
        float a = 0.f;
        if (f < 100) {
            const float* wr = &giw[f * 100 + part * 25];
            const float* sp = &shm[part * 25];
#pragma unroll
            for (int j = 0; j < 25; j++) a = fmaf(wr[j], sp[j], a);
        }
        a += __shfl_xor_sync(0xffffffffu, a, 1);
        a += __shfl_xor_sync(0xffffffffu, a, 2);
        if (part == 0 && f < 100) sg[f] = fmaxf(a + gib[f], 0.f);
    }
    __syncthreads();
    {
        float a = 0.f;
        if (f < 100) {
            const float* wr = &c3w[f * 200 + part * 25];
            const float* sp = &sg[part * 25];
#pragma unroll
            for (int j = 0; j < 25; j++) a = fmaf(wr[j], sp[j], a);
        }
        a += __shfl_xor_sync(0xffffffffu, a, 1);
        a += __shfl_xor_sync(0xffffffffu, a, 2);
        if (part == 0 && f < 100) g_gz[b * 128 + f] = a + c3b[f];
    }
}

// ---------------- KCF: fused conv2 -> li -> conv3 -> logits (R12 proven) ---
#define CF_WA   31680
#define CF_WB   58560
#define CF_B2   85440
#define CF_BL   85952
#define CF_GZ   86464
#define CF_C4   86976
#define CF_LOG  87488
#define CF_SMEM 88000
__global__ __launch_bounds__(256, 2) void kCF(const float* __restrict__ b2,
                                              const float* __restrict__ lb,
                                              const float* __restrict__ c4w,
                                              const float* __restrict__ c4b) {
    extern __shared__ char sm[];
    uint32_t* sD32 = (uint32_t*)sm;                 // D1, then H2, then Loc
    __nv_bfloat16* sD16 = (__nv_bfloat16*)sm;
    float* sB2 = (float*)(sm + CF_B2);
    float* sBL = (float*)(sm + CF_BL);
    float* sGz = (float*)(sm + CF_GZ);
    float* sC4 = (float*)(sm + CF_C4);
    float* sLog = (float*)(sm + CF_LOG);
    const int cx = blockIdx.x, b = blockIdx.y, tid = threadIdx.x;
    const int lane = tid & 31, wid = tid >> 5, wf = wid & 1, wl = wid >> 1;
    const int l0 = cx * 128;
    const uint4* src = (const uint4*)(g_h1 + (size_t)b * L_ * 56);
    const uint32_t sD_u = smem_u32(sm);
    uint32_t wcur = sD_u + CF_WA, wnext = sD_u + CF_WB;

    stage_w(wcur, wsrc(0), tid);
    for (int idx = tid; idx < 132 * 15; idx += 256) {
        int r = idx / 15, q = idx - r * 15;
        int l = l0 - 2 + r;
        bool ok = (q < 14) && ((unsigned)l < (unsigned)L_);
        const void* s = ok ? (const void*)(src + (size_t)l * 14 + q) : (const void*)src;
        cpa16z(sD_u + (uint32_t)idx * 16, s, ok ? 16 : 0);
    }
    cpa_commit();
    if (tid < 128) {
        sB2[tid] = (tid < 100) ? b2[tid] : 0.f;
        sBL[tid] = (tid < 100) ? lb[tid] : 0.f;
        sGz[tid] = (tid < 100) ? g_gz[b * 128 + tid] : 0.f;
        sC4[tid] = (tid < 100) ? c4w[tid] : 0.f;
        sLog[tid] = 0.f;
    }
    cpa_wait0();
    __syncthreads();

    const int lq = lane >> 2, fq = lane & 3;
    const int hcol = tid / 112, hch = tid - hcol * 112;
    const bool hok = (tid < 224) &&
        ((hcol == 0) ? (l0 - 1 >= 0) : (l0 + 128 < L_));
    float hs = 0.f;

    float d[2][7][4];
    ZERO_D(d);
    for (int t = 0; t < 3; t++) {
        stage_w(wnext, wsrc(t + 1), tid);
        gemm_tap(sD_u, wcur, d, 1 + t, lane, wf, wl);
        if (hok) {
            const uint32_t* dr = sD32 + ((hcol ? 129 : 0) + t) * 60;
            const uint4* wr4 = (const uint4*)(g_Wb2 + t * 15360 + hch * 120);
#pragma unroll
            for (int q = 0; q < 13; q++) {
                uint4 w = wr4[q];
                float2 w0 = bf2f(w.x), w1 = bf2f(w.y), w2_ = bf2f(w.z), w3_ = bf2f(w.w);
                float2 a0 = bf2f(dr[4 * q]), a1 = bf2f(dr[4 * q + 1]);
                float2 a2 = bf2f(dr[4 * q + 2]), a3 = bf2f(dr[4 * q + 3]);
                hs += a0.x * w0.x + a0.y * w0.y + a1.x * w1.x + a1.y * w1.y
                    + a2.x * w2_.x + a2.y * w2_.y + a3.x * w3_.x + a3.y * w3_.y;
            }
        }
        cpa_wait0();
        __syncthreads();
        uint32_t tmp = wcur; wcur = wnext; wnext = tmp;
    }
#pragma unroll
    for (int mi = 0; mi < 2; mi++) {
        int lr = wl * 32 + mi * 16 + lq;
#pragma unroll
        for (int nf = 0; nf < 7; nf++) {
            int fp = wf * 28 + nf * 4 + fq;
            float bx = sB2[2 * fp], by = sB2[2 * fp + 1];
            float v0 = fmaxf(d[mi][nf][0] + bx, 0.f), v1 = fmaxf(d[mi][nf][1] + by, 0.f);
            float v2 = fmaxf(d[mi][nf][2] + bx, 0.f), v3 = fmaxf(d[mi][nf][3] + by, 0.f);
            __nv_bfloat162 p0 = __floats2bfloat162_rn(v0, v1);
            __nv_bfloat162 p1 = __floats2bfloat162_rn(v2, v3);
            sD32[(lr + 1) * 60 + fp] = *(uint32_t*)&p0;
            sD32[(lr + 9) * 60 + fp] = *(uint32_t*)&p1;
        }
    }
    if (tid < 224) {
        float v = hok ? fmaxf(hs + sB2[hch], 0.f) : 0.f;
        sD16[(hcol ? 129 : 0) * 120 + hch] = __float2bfloat16(v);
    }
    __syncthreads();

    ZERO_D(d);
    for (int t = 0; t < 3; t++) {
        if (t < 2) stage_w(wnext, wsrc(t + 4), tid);
        else stage_w(wnext, wsrc(6), tid);
        gemm_tap(sD_u, wcur, d, t, lane, wf, wl);
        cpa_wait0();
        __syncthreads();
        uint32_t tmp = wcur; wcur = wnext; wnext = tmp;
    }
#pragma unroll
    for (int mi = 0; mi < 2; mi++) {
        int lr = wl * 32 + mi * 16 + lq;
#pragma unroll
        for (int nf = 0; nf < 7; nf++) {
            int fp = wf * 28 + nf * 4 + fq;
            float bx = sBL[2 * fp], by = sBL[2 * fp + 1];
            float v0 = fmaxf(d[mi][nf][0] + bx, 0.f), v1 = fmaxf(d[mi][nf][1] + by, 0.f);
            float v2 = fmaxf(d[mi][nf][2] + bx, 0.f), v3 = fmaxf(d[mi][nf][3] + by, 0.f);
            __nv_bfloat162 p0 = __floats2bfloat162_rn(v0, v1);
            __nv_bfloat162 p1 = __floats2bfloat162_rn(v2, v3);
            sD32[lr * 60 + fp] = *(uint32_t*)&p0;
            sD32[(lr + 8) * 60 + fp] = *(uint32_t*)&p1;
        }
    }
    __syncthreads();

    ZERO_D(d);
    gemm_tap(sD_u, wcur, d, 0, lane, wf, wl);
#pragma unroll
    for (int mi = 0; mi < 2; mi++) {
        int lr = wl * 32 + mi * 16 + lq;
        float pA = 0.f, pB = 0.f;
#pragma unroll
        for (int nf = 0; nf < 7; nf++) {
            int f0 = wf * 56 + nf * 8 + fq * 2;
            float g0 = sGz[f0], g1 = sGz[f0 + 1];
            float c0 = sC4[f0], c1 = sC4[f0 + 1];
            pA += c0 * fmaxf(d[mi][nf][0] + g0, 0.f) + c1 * fmaxf(d[mi][nf][1] + g1, 0.f);
            pB += c0 * fmaxf(d[mi][nf][2] + g0, 0.f) + c1 * fmaxf(d[mi][nf][3] + g1, 0.f);
        }
        pA += __shfl_xor_sync(0xffffffffu, pA, 1);
        pA += __shfl_xor_sync(0xffffffffu, pA, 2);
        pB += __shfl_xor_sync(0xffffffffu, pB, 1);
        pB += __shfl_xor_sync(0xffffffffu, pB, 2);
        if (fq == 0) {
            atomicAdd(&sLog[lr], pA);
            atomicAdd(&sLog[lr + 8], pB);
        }
    }
    __syncthreads();
    if (tid < 128) g_logits[b * L_ + l0 + tid] = sLog[tid] + c4b[0];
}

// ---------------- block sum (256 threads) ----------------------------------
__device__ __forceinline__ float bsum256(float v, float* sred) {
#pragma unroll
    for (int o = 16; o > 0; o >>= 1) v += __shfl_xor_sync(0xffffffffu, v, o);
    int w = threadIdx.x >> 5;
    if ((threadIdx.x & 31) == 0) sred[w] = v;
    __syncthreads();
    if (threadIdx.x == 0) {
        float t = sred[0];
#pragma unroll
        for (int i = 1; i < 8; i++) t += sred[i];
        sred[0] = t;
    }
    __syncthreads();
    float r = sred[0];
    __syncthreads();
    return r;
}

// ---------------- KS: warp-per-k gumbel + pooling + MLP + sigmoid ----------
__global__ __launch_bounds__(256) void kS(const float* __restrict__ u,
                                          const int* __restrict__ x,
                                          const float* __restrict__ emb,
                                          const float* __restrict__ f1w,
                                          const float* __restrict__ f1b,
                                          const float* __restrict__ hw,
                                          const float* __restrict__ hb,
                                          float* __restrict__ cs_out,
                                          float* __restrict__ out) {
    const int b = blockIdx.x, tid = threadIdx.x;
    const int lane = tid & 31, wid = tid >> 5;
    __shared__ float slog[L_];
    __shared__ float scs[L_];
    __shared__ int sx[L_];
    __shared__ float spool2[2][128];
    __shared__ float sh[100];
    __shared__ float sred[8];
    const float EPS = 1.1920929e-07f;
    const float invT = 1.0f / 0.3f;

    for (int l = tid; l < L_; l += 256) {
        slog[l] = g_logits[b * L_ + l];
        sx[l] = x[b * L_ + l];
        scs[l] = 0.f;
    }
    __syncthreads();

    // each warp handles k = wid and k = wid+8; shfl-only reductions
    for (int k = wid; k < KK_; k += 8) {
        const float* ub = u + (b * KK_ + k) * L_;
        float nv[16];
        float mx = -1e30f;
#pragma unroll
        for (int j = 0; j < 16; j++) {
            int l = lane + 32 * j;
            float uu = fminf(fmaxf(ub[l], EPS), 1.0f - EPS);
            nv[j] = (-logf(-logf(uu)) + slog[l]) * invT;
            mx = fmaxf(mx, nv[j]);
        }
#pragma unroll
        for (int o = 16; o > 0; o >>= 1) mx = fmaxf(mx, __shfl_xor_sync(0xffffffffu, mx, o));
        float s = 0.f;
#pragma unroll
        for (int j = 0; j < 16; j++) {
            nv[j] = expf(nv[j] - mx);
            s += nv[j];
        }
#pragma unroll
        for (int o = 16; o > 0; o >>= 1) s += __shfl_xor_sync(0xffffffffu, s, o);
        float rs = 1.f / s;
#pragma unroll
        for (int j = 0; j < 16; j++)
            atomicMax((int*)&scs[lane + 32 * j], __float_as_int(nv[j] * rs));
    }
    __syncthreads();
    cs_out[b * L_ + tid] = scs[tid];
    cs_out[b * L_ + tid + 256] = scs[tid + 256];

    // pooling: 2 halves of L across 256 threads
    const int half = tid >> 7, c = tid & 127;
    if (c < 100) {
        float acc = 0.f;
        const int lb_ = half * 256;
        for (int l = lb_; l < lb_ + 256; l += 8) {
            float p[8];
#pragma unroll
            for (int q = 0; q < 8; q++) p[q] = emb[sx[l + q] * 100 + c];
#pragma unroll
            for (int q = 0; q < 8; q++) acc = fmaf(scs[l + q], p[q], acc);
        }
        spool2[half][c] = acc;
    }
    __syncthreads();
    if (tid < 100) {
        float pooled_own = (spool2[0][tid] + spool2[1][tid]) * (1.f / (float)L_);
        spool2[0][tid] = pooled_own;
    }
    __syncthreads();
    if (tid < 100) {
        float a = f1b[tid];
        const float* wr = &f1w[tid * 100];
        for (int e = 0; e < 100; e++) a = fmaf(wr[e], spool2[0][e], a);
        sh[tid] = fmaxf(a, 0.f);
    }
    __syncthreads();
    float hv = (tid < 100) ? hw[tid] * sh[tid] : 0.f;
    hv = bsum256(hv, sred);
    if (tid == 0) out[b] = 1.f / (1.f + expf(-(hv + hb[0])));
}

// ---------------- launch ----------------------------------------------------
extern "C" void kernel_launch(void* const* d_in, const int* in_sizes, int n_in,
                              void* d_out, int out_size) {
    const int*   x   = (const int*)  d_in[0];
    const float* u   = (const float*)d_in[1];
    const float* emb = (const float*)d_in[2];
    const float* c1w = (const float*)d_in[3];
    const float* c1b = (const float*)d_in[4];
    const float* giw = (const float*)d_in[5];
    const float* gib = (const float*)d_in[6];
    const float* c2w = (const float*)d_in[7];
    const float* c2b = (const float*)d_in[8];
    const float* liw = (const float*)d_in[9];
    const float* lib = (const float*)d_in[10];
    const float* c3w = (const float*)d_in[11];
    const float* c3b = (const float*)d_in[12];
    const float* c4w = (const float*)d_in[13];
    const float* c4b = (const float*)d_in[14];
    const float* f1w = (const float*)d_in[15];
    const float* f1b = (const float*)d_in[16];
    const float* hw  = (const float*)d_in[17];
    const float* hb  = (const float*)d_in[18];

    float* out = (float*)d_out;          // [B,1] first
    float* cs  = out + B_;               // then csamples [B,L]

    cudaFuncSetAttribute(kC1, cudaFuncAttributeMaxDynamicSharedMemorySize, C1_SMEM);
    cudaFuncSetAttribute(kCF, cudaFuncAttributeMaxDynamicSharedMemorySize, CF_SMEM);

    k0_prep<<<593, 256>>>(c1w, c2w, liw, c3w);
    k0e<<<(100000 * 56 + 255) / 256, 256>>>(emb);
    kC1<<<dim3(4, B_), 256, C1_SMEM>>>(x, c1b);
    kG<<<B_, 512>>>(giw, gib, c3w, c3b);
    kCF<<<dim3(4, B_), 256, CF_SMEM>>>(c2b, lib, c4w, c4b);
    kS<<<B_, 256>>>(u, x, emb, f1w, f1b, hw, hb, cs, out);
}